// round 13
// baseline (speedup 1.0000x reference)
#include <cuda_runtime.h>
#include <cuda_fp16.h>
#include <cstdint>
#include <cstring>

#define N_NODES   100000
#define N_EDGES   1600000
#define D         64
#define NEG_SLOPE 0.2f
#define BUCKET    64        // max in-degree slots (Poisson(16): P(>64) ~ 1e-29)

typedef unsigned long long ull;

// packed fp32x2 FMA (sm_103a FFMA2 — PTX-only pattern)
#define FMA2(d, a, b) \
    asm("fma.rn.f32x2 %0, %1, %2, %0;" : "+l"(d) : "l"(a), "l"(b))
#define UNPACK2(lo, hi, in) \
    asm("mov.b64 {%0, %1}, %2;" : "=f"(lo), "=f"(hi) : "l"(in))
// packed fp16x2 FMA / ADD
#define HFMA2(d, a, b) \
    asm("fma.rn.f16x2 %0, %1, %2, %0;" : "+r"(d) : "r"(a), "r"(b))
#define HADD2(d, a, b) \
    asm("add.rn.f16x2 %0, %1, %2;" : "=r"(d) : "r"(a), "r"(b))

__device__ __forceinline__ uint32_t h2_bits(__half2 h) {
    uint32_t u;
    memcpy(&u, &h, 4);
    return u;
}
__device__ __forceinline__ __half2 bits_h2(uint32_t u) {
    __half2 h;
    memcpy(&h, &u, 4);
    return h;
}

// Scratch (allocation-free rule: __device__ globals)
__device__ int     g_cnt[N_NODES];                       // in-degree counters
__device__ float   g_denom[N_NODES];                     // fp32 softmax denominators
__device__ uint2   g_csr[(size_t)N_NODES * BUCKET];      // buckets (src, half2(ex))
__device__ __half2 g_gh[(size_t)N_NODES * 32];           // feat @ W_neigh^T (fp16)

// ---------------------------------------------------------------------------
// K1: single-pass bucket build + fp32 denominator.
//   bucket record = (src, half2(ex)) so aggregate's loop has zero converts.
// ---------------------------------------------------------------------------
__global__ void place_kernel(const float* __restrict__ rel,
                             const float* __restrict__ attn,
                             const int*   __restrict__ src,
                             const int*   __restrict__ dst) {
    int i = (blockIdx.x * blockDim.x + threadIdx.x) * 2;
    if (i >= N_EDGES) return;
    float a0 = __ldg(&attn[0]);
    float a1 = __ldg(&attn[1]);
    float4 r = *reinterpret_cast<const float4*>(rel + i * 2);  // edges i, i+1
    int2 s2 = *reinterpret_cast<const int2*>(src + i);
    int2 d2 = *reinterpret_cast<const int2*>(dst + i);

    float e0 = r.x * a0 + r.y * a1;
    float e1 = r.z * a0 + r.w * a1;
    e0 = (e0 > 0.0f) ? e0 : NEG_SLOPE * e0;
    e1 = (e1 > 0.0f) ? e1 : NEG_SLOPE * e1;
    float ex0 = __expf(e0);
    float ex1 = __expf(e1);

    atomicAdd(&g_denom[d2.x], ex0);
    atomicAdd(&g_denom[d2.y], ex1);
    int p0 = atomicAdd(&g_cnt[d2.x], 1);
    int p1 = atomicAdd(&g_cnt[d2.y], 1);
    if (p0 < BUCKET)
        g_csr[(size_t)d2.x * BUCKET + p0] =
            make_uint2((uint32_t)s2.x, h2_bits(__float2half2_rn(ex0)));
    if (p1 < BUCKET)
        g_csr[(size_t)d2.y * BUCKET + p1] =
            make_uint2((uint32_t)s2.y, h2_bits(__float2half2_rn(ex1)));
}

// ---------------------------------------------------------------------------
// GEMM core (R8-proven inner loop, single weight matrix).
// 64 nodes/block, 128 threads, thread = 4 cols x 8 nodes, packed f32x2 FMA.
// SELF variant RED-adds into zeroed `out`; neigh variant stores fp16 g_gh.
// ---------------------------------------------------------------------------
#define GEMM_SMEM_BYTES (64 * 130 * 4 + 64 * 64 * 4)    // 49664 B -> 4 CTA/SM

template <bool SELF>
__device__ __forceinline__ void gemm_core(
    const float* __restrict__ feat,
    const float* __restrict__ W,
    const float* __restrict__ bs, const float* __restrict__ bn,
    float* __restrict__ out) {
    extern __shared__ float smem[];
    float (*sF2)[130] = (float(*)[130])smem;                 // dup feat [k][2n+h]
    float (*sW)[64]   = (float(*)[64])(smem + 64 * 130);     // transposed [k][o]

    const int t = threadIdx.x;
    const int nodeBase = blockIdx.x * 64;

    for (int i = t; i < 4096; i += 128) {
        int o = i >> 6, k = i & 63;
        int col = (o & 3) | ((((o >> 2) + (k & 15)) & 15) << 2);
        sW[k][col] = W[i];
    }
    for (int i = t; i < 4096; i += 128) {
        int n = i >> 6, k = i & 63;
        int node = nodeBase + n;
        float v = (node < N_NODES) ? __ldg(&feat[(size_t)node * D + k]) : 0.f;
        *reinterpret_cast<float2*>(&sF2[k][n * 2]) = make_float2(v, v);
    }
    __syncthreads();

    const int oc = (t & 15) * 4;
    const int nr = t >> 4;

    ull acc[8][2] = {};

    #pragma unroll 8
    for (int k = 0; k < 64; k++) {
        const int g4 = (((oc >> 2) + (k & 15)) & 15) << 2;
        ulonglong2 w = *reinterpret_cast<const ulonglong2*>(&sW[k][g4]);
        const float* frow = &sF2[k][nr * 16];
        #pragma unroll
        for (int j = 0; j < 8; j++) {
            ull f = *reinterpret_cast<const ull*>(frow + j * 2);
            FMA2(acc[j][0], f, w.x);
            FMA2(acc[j][1], f, w.y);
        }
    }

    float b0 = 0.f, b1 = 0.f, b2 = 0.f, b3 = 0.f;
    if (SELF) {
        b0 = __ldg(&bs[oc])     + __ldg(&bn[oc]);
        b1 = __ldg(&bs[oc + 1]) + __ldg(&bn[oc + 1]);
        b2 = __ldg(&bs[oc + 2]) + __ldg(&bn[oc + 2]);
        b3 = __ldg(&bs[oc + 3]) + __ldg(&bn[oc + 3]);
    }

    #pragma unroll
    for (int j = 0; j < 8; j++) {
        int node = nodeBase + nr * 8 + j;
        if (node < N_NODES) {
            float v0, v1, v2, v3;
            UNPACK2(v0, v1, acc[j][0]);
            UNPACK2(v2, v3, acc[j][1]);
            if (SELF) {
                float* p = out + (size_t)node * D + oc;
                asm volatile("red.global.add.v4.f32 [%0], {%1,%2,%3,%4};"
                             :: "l"(p), "f"(v0 + b0), "f"(v1 + b1),
                                "f"(v2 + b2), "f"(v3 + b3) : "memory");
            } else {
                __half2 h01 = __floats2half2_rn(v0, v1);
                __half2 h23 = __floats2half2_rn(v2, v3);
                *reinterpret_cast<uint2*>(&g_gh[(size_t)node * 32 + (oc >> 1)]) =
                    make_uint2(h2_bits(h01), h2_bits(h23));
            }
        }
    }
}

__global__ __launch_bounds__(128) void neigh_gemm_kernel(
    const float* __restrict__ feat, const float* __restrict__ Wn) {
    gemm_core<false>(feat, Wn, nullptr, nullptr, nullptr);
}

__global__ __launch_bounds__(128) void self_gemm_kernel(
    const float* __restrict__ feat, const float* __restrict__ Ws,
    const float* __restrict__ bs, const float* __restrict__ bn,
    float* __restrict__ out) {
    gemm_core<true>(feat, Ws, bs, bn, out);
}

// ---------------------------------------------------------------------------
// K3: gather-aggregate v5 — fp16 HFMA2, zero converts, precomputed denom,
//     TWO warps per node (interleaved 4-edge slabs).
//   lane = h*8 + c : h = edge slot, c = dim group (8 dims = LDG.128).
//   warp half 0 covers slabs [0..3],[8..11],...; half 1 covers [4..7],...
// ---------------------------------------------------------------------------
__global__ __launch_bounds__(256) void aggregate_kernel(float* __restrict__ out) {
    int gw = (blockIdx.x * blockDim.x + threadIdx.x) >> 5;
    int node = gw >> 1;
    if (node >= N_NODES) return;
    const int half = gw & 1;
    const int lane = threadIdx.x & 31;
    const int h = lane >> 3;       // edge slot 0..3
    const int c = lane & 7;        // dim group (8 dims)

    int cnt = g_cnt[node];
    if (cnt > BUCKET) cnt = BUCKET;
    const int start = half * 4;
    if (start >= cnt) return;
    const uint2* bucket = &g_csr[(size_t)node * BUCKET];

    uint32_t acc0 = 0, acc1 = 0, acc2 = 0, acc3 = 0;   // half2 accumulators

    #pragma unroll 2
    for (int j = start; j < cnt; j += 8) {
        int idx = j + h;
        uint2 p = (idx < cnt) ? __ldg(&bucket[idx]) : make_uint2(0u, 0u);
        uint4 hv = __ldg(reinterpret_cast<const uint4*>(
            &g_gh[(size_t)p.x * 32 + c * 4]));   // 8 dims, 16B aligned
        HFMA2(acc0, hv.x, p.y);
        HFMA2(acc1, hv.y, p.y);
        HFMA2(acc2, hv.z, p.y);
        HFMA2(acc3, hv.w, p.y);
    }

    // Combine the 4 edge slots (h) in fp16 via shfl-xor 8, 16
    uint32_t o0, o1, o2, o3;
    o0 = __shfl_xor_sync(0xffffffffu, acc0, 8);  HADD2(acc0, acc0, o0);
    o1 = __shfl_xor_sync(0xffffffffu, acc1, 8);  HADD2(acc1, acc1, o1);
    o2 = __shfl_xor_sync(0xffffffffu, acc2, 8);  HADD2(acc2, acc2, o2);
    o3 = __shfl_xor_sync(0xffffffffu, acc3, 8);  HADD2(acc3, acc3, o3);
    o0 = __shfl_xor_sync(0xffffffffu, acc0, 16); HADD2(acc0, acc0, o0);
    o1 = __shfl_xor_sync(0xffffffffu, acc1, 16); HADD2(acc1, acc1, o1);
    o2 = __shfl_xor_sync(0xffffffffu, acc2, 16); HADD2(acc2, acc2, o2);
    o3 = __shfl_xor_sync(0xffffffffu, acc3, 16); HADD2(acc3, acc3, o3);

    if (h == 0) {
        const float inv = 1.0f / __ldg(&g_denom[node]);
        float2 f0 = __half22float2(bits_h2(acc0));
        float2 f1 = __half22float2(bits_h2(acc1));
        float2 f2 = __half22float2(bits_h2(acc2));
        float2 f3 = __half22float2(bits_h2(acc3));
        float* p = out + (size_t)node * D + c * 8;
        asm volatile("red.global.add.v4.f32 [%0], {%1,%2,%3,%4};"
                     :: "l"(p), "f"(f0.x * inv), "f"(f0.y * inv),
                        "f"(f1.x * inv), "f"(f1.y * inv) : "memory");
        asm volatile("red.global.add.v4.f32 [%0], {%1,%2,%3,%4};"
                     :: "l"(p + 4), "f"(f2.x * inv), "f"(f2.y * inv),
                        "f"(f3.x * inv), "f"(f3.y * inv) : "memory");
    }
}

// ---------------------------------------------------------------------------
// Launch schedule (out zeroed; self GEMM and aggregate RED-add in any order):
//   s2:   neigh_gemm --evNeigh--> (wait evMemset) self_gemm --evJoin-->
//   main: memsets --evMemset--> place --(wait evNeigh)--> aggregate
//         --(wait evJoin)
// ---------------------------------------------------------------------------
extern "C" void kernel_launch(void* const* d_in, const int* in_sizes, int n_in,
                              void* d_out, int out_size) {
    const float* feat = (const float*)d_in[0];
    const float* rel  = (const float*)d_in[1];
    const float* Ws   = (const float*)d_in[2];
    const float* bs   = (const float*)d_in[3];
    const float* Wn   = (const float*)d_in[4];
    const float* bn   = (const float*)d_in[5];
    const float* attn = (const float*)d_in[6];
    const int*   src  = (const int*)d_in[7];
    const int*   dst  = (const int*)d_in[8];
    float* out = (float*)d_out;

    static void*        cnt_addr = nullptr;
    static void*        den_addr = nullptr;
    static cudaStream_t s2;
    static cudaEvent_t  evFork, evNeigh, evMemset, evJoin;
    if (!cnt_addr) {
        cudaFuncSetAttribute(neigh_gemm_kernel,
                             cudaFuncAttributeMaxDynamicSharedMemorySize,
                             GEMM_SMEM_BYTES);
        cudaFuncSetAttribute(self_gemm_kernel,
                             cudaFuncAttributeMaxDynamicSharedMemorySize,
                             GEMM_SMEM_BYTES);
        cudaGetSymbolAddress(&cnt_addr, g_cnt);
        cudaGetSymbolAddress(&den_addr, g_denom);
        cudaStreamCreateWithFlags(&s2, cudaStreamNonBlocking);
        cudaEventCreateWithFlags(&evFork,   cudaEventDisableTiming);
        cudaEventCreateWithFlags(&evNeigh,  cudaEventDisableTiming);
        cudaEventCreateWithFlags(&evMemset, cudaEventDisableTiming);
        cudaEventCreateWithFlags(&evJoin,   cudaEventDisableTiming);
    }

    // Fork side stream
    cudaEventRecord(evFork, 0);
    cudaStreamWaitEvent(s2, evFork, 0);
    neigh_gemm_kernel<<<(N_NODES + 63) / 64, 128, GEMM_SMEM_BYTES, s2>>>(feat, Wn);
    cudaEventRecord(evNeigh, s2);

    // Main: zero counters, denominators and output, then bucket build
    cudaMemsetAsync(cnt_addr, 0, N_NODES * sizeof(int));
    cudaMemsetAsync(den_addr, 0, N_NODES * sizeof(float));
    cudaMemsetAsync(out, 0, (size_t)N_NODES * D * sizeof(float));
    cudaEventRecord(evMemset, 0);
    place_kernel<<<(N_EDGES / 2 + 255) / 256, 256>>>(rel, attn, src, dst);

    // Side stream: self GEMM REDs into out (needs out zeroed)
    cudaStreamWaitEvent(s2, evMemset, 0);
    self_gemm_kernel<<<(N_NODES + 63) / 64, 128, GEMM_SMEM_BYTES, s2>>>(
        feat, Ws, bs, bn, out);
    cudaEventRecord(evJoin, s2);

    // Aggregate needs neigh GEMM + buckets; overlaps with self GEMM
    cudaStreamWaitEvent(0, evNeigh, 0);
    aggregate_kernel<<<(N_NODES * 2 * 32 + 255) / 256, 256>>>(out);

    // Final join: self GEMM must complete before harness reads out
    cudaStreamWaitEvent(0, evJoin, 0);
}

// round 14
// speedup vs baseline: 1.1113x; 1.1113x over previous
#include <cuda_runtime.h>
#include <cuda_fp16.h>
#include <cstdint>
#include <cstring>

#define N_NODES   100000
#define N_EDGES   1600000
#define D         64
#define NEG_SLOPE 0.2f
#define BUCKET    64        // max in-degree slots (Poisson(16): P(>64) ~ 1e-29)

typedef unsigned long long ull;

// packed fp32x2 FMA (sm_103a FFMA2 — PTX-only pattern)
#define FMA2(d, a, b) \
    asm("fma.rn.f32x2 %0, %1, %2, %0;" : "+l"(d) : "l"(a), "l"(b))
#define UNPACK2(lo, hi, in) \
    asm("mov.b64 {%0, %1}, %2;" : "=f"(lo), "=f"(hi) : "l"(in))
// packed fp16x2 FMA / ADD
#define HFMA2(d, a, b) \
    asm("fma.rn.f16x2 %0, %1, %2, %0;" : "+r"(d) : "r"(a), "r"(b))
#define HADD2(d, a, b) \
    asm("add.rn.f16x2 %0, %1, %2;" : "=r"(d) : "r"(a), "r"(b))

__device__ __forceinline__ uint32_t h2_bits(__half2 h) {
    uint32_t u;
    memcpy(&u, &h, 4);
    return u;
}
__device__ __forceinline__ __half2 bits_h2(uint32_t u) {
    __half2 h;
    memcpy(&h, &u, 4);
    return h;
}

// Scratch (allocation-free rule: __device__ globals)
__device__ int     g_cnt[N_NODES];                       // in-degree counters
__device__ float   g_denom[N_NODES];                     // fp32 softmax denominators
__device__ uint2   g_csr[(size_t)N_NODES * BUCKET];      // buckets (src, half2(ex))
__device__ __half2 g_gh[(size_t)N_NODES * 32];           // feat @ W_neigh^T (fp16)

// ---------------------------------------------------------------------------
// K1: single-pass bucket build + fp32 denominator.
//   bucket record = (src, half2(ex)) so aggregate's loop has zero converts.
// ---------------------------------------------------------------------------
__global__ void place_kernel(const float* __restrict__ rel,
                             const float* __restrict__ attn,
                             const int*   __restrict__ src,
                             const int*   __restrict__ dst) {
    int i = (blockIdx.x * blockDim.x + threadIdx.x) * 2;
    if (i >= N_EDGES) return;
    float a0 = __ldg(&attn[0]);
    float a1 = __ldg(&attn[1]);
    float4 r = *reinterpret_cast<const float4*>(rel + i * 2);  // edges i, i+1
    int2 s2 = *reinterpret_cast<const int2*>(src + i);
    int2 d2 = *reinterpret_cast<const int2*>(dst + i);

    float e0 = r.x * a0 + r.y * a1;
    float e1 = r.z * a0 + r.w * a1;
    e0 = (e0 > 0.0f) ? e0 : NEG_SLOPE * e0;
    e1 = (e1 > 0.0f) ? e1 : NEG_SLOPE * e1;
    float ex0 = __expf(e0);
    float ex1 = __expf(e1);

    atomicAdd(&g_denom[d2.x], ex0);
    atomicAdd(&g_denom[d2.y], ex1);
    int p0 = atomicAdd(&g_cnt[d2.x], 1);
    int p1 = atomicAdd(&g_cnt[d2.y], 1);
    if (p0 < BUCKET)
        g_csr[(size_t)d2.x * BUCKET + p0] =
            make_uint2((uint32_t)s2.x, h2_bits(__float2half2_rn(ex0)));
    if (p1 < BUCKET)
        g_csr[(size_t)d2.y * BUCKET + p1] =
            make_uint2((uint32_t)s2.y, h2_bits(__float2half2_rn(ex1)));
}

// ---------------------------------------------------------------------------
// GEMM core (R8-proven inner loop, single weight matrix).
// 64 nodes/block, 128 threads, thread = 4 cols x 8 nodes, packed f32x2 FMA.
// SELF variant RED-adds into zeroed `out`; neigh variant stores fp16 g_gh.
// ---------------------------------------------------------------------------
#define GEMM_SMEM_BYTES (64 * 130 * 4 + 64 * 64 * 4)    // 49664 B -> 4 CTA/SM

template <bool SELF>
__device__ __forceinline__ void gemm_core(
    const float* __restrict__ feat,
    const float* __restrict__ W,
    const float* __restrict__ bs, const float* __restrict__ bn,
    float* __restrict__ out) {
    extern __shared__ float smem[];
    float (*sF2)[130] = (float(*)[130])smem;                 // dup feat [k][2n+h]
    float (*sW)[64]   = (float(*)[64])(smem + 64 * 130);     // transposed [k][o]

    const int t = threadIdx.x;
    const int nodeBase = blockIdx.x * 64;

    for (int i = t; i < 4096; i += 128) {
        int o = i >> 6, k = i & 63;
        int col = (o & 3) | ((((o >> 2) + (k & 15)) & 15) << 2);
        sW[k][col] = W[i];
    }
    for (int i = t; i < 4096; i += 128) {
        int n = i >> 6, k = i & 63;
        int node = nodeBase + n;
        float v = (node < N_NODES) ? __ldg(&feat[(size_t)node * D + k]) : 0.f;
        *reinterpret_cast<float2*>(&sF2[k][n * 2]) = make_float2(v, v);
    }
    __syncthreads();

    const int oc = (t & 15) * 4;
    const int nr = t >> 4;

    ull acc[8][2] = {};

    #pragma unroll 8
    for (int k = 0; k < 64; k++) {
        const int g4 = (((oc >> 2) + (k & 15)) & 15) << 2;
        ulonglong2 w = *reinterpret_cast<const ulonglong2*>(&sW[k][g4]);
        const float* frow = &sF2[k][nr * 16];
        #pragma unroll
        for (int j = 0; j < 8; j++) {
            ull f = *reinterpret_cast<const ull*>(frow + j * 2);
            FMA2(acc[j][0], f, w.x);
            FMA2(acc[j][1], f, w.y);
        }
    }

    float b0 = 0.f, b1 = 0.f, b2 = 0.f, b3 = 0.f;
    if (SELF) {
        b0 = __ldg(&bs[oc])     + __ldg(&bn[oc]);
        b1 = __ldg(&bs[oc + 1]) + __ldg(&bn[oc + 1]);
        b2 = __ldg(&bs[oc + 2]) + __ldg(&bn[oc + 2]);
        b3 = __ldg(&bs[oc + 3]) + __ldg(&bn[oc + 3]);
    }

    #pragma unroll
    for (int j = 0; j < 8; j++) {
        int node = nodeBase + nr * 8 + j;
        if (node < N_NODES) {
            float v0, v1, v2, v3;
            UNPACK2(v0, v1, acc[j][0]);
            UNPACK2(v2, v3, acc[j][1]);
            if (SELF) {
                float* p = out + (size_t)node * D + oc;
                asm volatile("red.global.add.v4.f32 [%0], {%1,%2,%3,%4};"
                             :: "l"(p), "f"(v0 + b0), "f"(v1 + b1),
                                "f"(v2 + b2), "f"(v3 + b3) : "memory");
            } else {
                __half2 h01 = __floats2half2_rn(v0, v1);
                __half2 h23 = __floats2half2_rn(v2, v3);
                *reinterpret_cast<uint2*>(&g_gh[(size_t)node * 32 + (oc >> 1)]) =
                    make_uint2(h2_bits(h01), h2_bits(h23));
            }
        }
    }
}

__global__ __launch_bounds__(128) void neigh_gemm_kernel(
    const float* __restrict__ feat, const float* __restrict__ Wn) {
    gemm_core<false>(feat, Wn, nullptr, nullptr, nullptr);
}

__global__ __launch_bounds__(128) void self_gemm_kernel(
    const float* __restrict__ feat, const float* __restrict__ Ws,
    const float* __restrict__ bs, const float* __restrict__ bn,
    float* __restrict__ out) {
    gemm_core<true>(feat, Ws, bs, bn, out);
}

// ---------------------------------------------------------------------------
// K3: gather-aggregate v6 — single warp/node (R12 structure), fp16 HFMA2,
//     zero in-loop converts, precomputed fp32 denom.
//   lane = h*8 + c : h = edge slot (4 edges/step), c = dim group (8 dims).
// ---------------------------------------------------------------------------
__global__ __launch_bounds__(256) void aggregate_kernel(float* __restrict__ out) {
    int node = (blockIdx.x * blockDim.x + threadIdx.x) >> 5;
    if (node >= N_NODES) return;
    const int lane = threadIdx.x & 31;
    const int h = lane >> 3;       // edge slot 0..3
    const int c = lane & 7;        // dim group (8 dims)

    int cnt = g_cnt[node];
    if (cnt == 0) return;
    if (cnt > BUCKET) cnt = BUCKET;
    const uint2* bucket = &g_csr[(size_t)node * BUCKET];

    uint32_t acc0 = 0, acc1 = 0, acc2 = 0, acc3 = 0;   // half2 accumulators

    #pragma unroll 2
    for (int j = 0; j < cnt; j += 4) {
        int idx = j + h;
        uint2 p = (idx < cnt) ? __ldg(&bucket[idx]) : make_uint2(0u, 0u);
        uint4 hv = __ldg(reinterpret_cast<const uint4*>(
            &g_gh[(size_t)p.x * 32 + c * 4]));   // 8 dims, 16B aligned
        HFMA2(acc0, hv.x, p.y);
        HFMA2(acc1, hv.y, p.y);
        HFMA2(acc2, hv.z, p.y);
        HFMA2(acc3, hv.w, p.y);
    }

    // Combine the 4 edge slots (h) in fp16 via shfl-xor 8, 16
    uint32_t o0, o1, o2, o3;
    o0 = __shfl_xor_sync(0xffffffffu, acc0, 8);  HADD2(acc0, acc0, o0);
    o1 = __shfl_xor_sync(0xffffffffu, acc1, 8);  HADD2(acc1, acc1, o1);
    o2 = __shfl_xor_sync(0xffffffffu, acc2, 8);  HADD2(acc2, acc2, o2);
    o3 = __shfl_xor_sync(0xffffffffu, acc3, 8);  HADD2(acc3, acc3, o3);
    o0 = __shfl_xor_sync(0xffffffffu, acc0, 16); HADD2(acc0, acc0, o0);
    o1 = __shfl_xor_sync(0xffffffffu, acc1, 16); HADD2(acc1, acc1, o1);
    o2 = __shfl_xor_sync(0xffffffffu, acc2, 16); HADD2(acc2, acc2, o2);
    o3 = __shfl_xor_sync(0xffffffffu, acc3, 16); HADD2(acc3, acc3, o3);

    if (h == 0) {
        const float inv = 1.0f / __ldg(&g_denom[node]);
        float2 f0 = __half22float2(bits_h2(acc0));
        float2 f1 = __half22float2(bits_h2(acc1));
        float2 f2 = __half22float2(bits_h2(acc2));
        float2 f3 = __half22float2(bits_h2(acc3));
        float* p = out + (size_t)node * D + c * 8;
        asm volatile("red.global.add.v4.f32 [%0], {%1,%2,%3,%4};"
                     :: "l"(p), "f"(f0.x * inv), "f"(f0.y * inv),
                        "f"(f1.x * inv), "f"(f1.y * inv) : "memory");
        asm volatile("red.global.add.v4.f32 [%0], {%1,%2,%3,%4};"
                     :: "l"(p + 4), "f"(f2.x * inv), "f"(f2.y * inv),
                        "f"(f3.x * inv), "f"(f3.y * inv) : "memory");
    }
}

// ---------------------------------------------------------------------------
// Launch schedule (out zeroed; self GEMM and aggregate RED-add in any order):
//   s2:   neigh_gemm --evNeigh--> (wait evMemset) self_gemm --evJoin-->
//   main: memsets --evMemset--> place --(wait evNeigh)--> aggregate
//         --(wait evJoin)
// ---------------------------------------------------------------------------
extern "C" void kernel_launch(void* const* d_in, const int* in_sizes, int n_in,
                              void* d_out, int out_size) {
    const float* feat = (const float*)d_in[0];
    const float* rel  = (const float*)d_in[1];
    const float* Ws   = (const float*)d_in[2];
    const float* bs   = (const float*)d_in[3];
    const float* Wn   = (const float*)d_in[4];
    const float* bn   = (const float*)d_in[5];
    const float* attn = (const float*)d_in[6];
    const int*   src  = (const int*)d_in[7];
    const int*   dst  = (const int*)d_in[8];
    float* out = (float*)d_out;

    static void*        cnt_addr = nullptr;
    static void*        den_addr = nullptr;
    static cudaStream_t s2;
    static cudaEvent_t  evFork, evNeigh, evMemset, evJoin;
    if (!cnt_addr) {
        cudaFuncSetAttribute(neigh_gemm_kernel,
                             cudaFuncAttributeMaxDynamicSharedMemorySize,
                             GEMM_SMEM_BYTES);
        cudaFuncSetAttribute(self_gemm_kernel,
                             cudaFuncAttributeMaxDynamicSharedMemorySize,
                             GEMM_SMEM_BYTES);
        cudaGetSymbolAddress(&cnt_addr, g_cnt);
        cudaGetSymbolAddress(&den_addr, g_denom);
        cudaStreamCreateWithFlags(&s2, cudaStreamNonBlocking);
        cudaEventCreateWithFlags(&evFork,   cudaEventDisableTiming);
        cudaEventCreateWithFlags(&evNeigh,  cudaEventDisableTiming);
        cudaEventCreateWithFlags(&evMemset, cudaEventDisableTiming);
        cudaEventCreateWithFlags(&evJoin,   cudaEventDisableTiming);
    }

    // Fork side stream
    cudaEventRecord(evFork, 0);
    cudaStreamWaitEvent(s2, evFork, 0);
    neigh_gemm_kernel<<<(N_NODES + 63) / 64, 128, GEMM_SMEM_BYTES, s2>>>(feat, Wn);
    cudaEventRecord(evNeigh, s2);

    // Main: zero counters, denominators and output, then bucket build
    cudaMemsetAsync(cnt_addr, 0, N_NODES * sizeof(int));
    cudaMemsetAsync(den_addr, 0, N_NODES * sizeof(float));
    cudaMemsetAsync(out, 0, (size_t)N_NODES * D * sizeof(float));
    cudaEventRecord(evMemset, 0);
    place_kernel<<<(N_EDGES / 2 + 255) / 256, 256>>>(rel, attn, src, dst);

    // Side stream: self GEMM REDs into out (needs out zeroed)
    cudaStreamWaitEvent(s2, evMemset, 0);
    self_gemm_kernel<<<(N_NODES + 63) / 64, 128, GEMM_SMEM_BYTES, s2>>>(
        feat, Ws, bs, bn, out);
    cudaEventRecord(evJoin, s2);

    // Aggregate needs neigh GEMM + buckets; overlaps with self GEMM
    cudaStreamWaitEvent(0, evNeigh, 0);
    aggregate_kernel<<<(N_NODES * 32 + 255) / 256, 256>>>(out);

    // Final join: self GEMM must complete before harness reads out
    cudaStreamWaitEvent(0, evJoin, 0);
}

// round 16
// speedup vs baseline: 1.7822x; 1.6038x over previous
#include <cuda_runtime.h>
#include <cuda_fp16.h>
#include <cstdint>
#include <cstring>

#define N_NODES   100000
#define N_EDGES   1600000
#define D         64
#define NEG_SLOPE 0.2f
#define BUCKET    64        // max in-degree slots (Poisson(16): P(>64) ~ 1e-29)

// packed fp16x2 FMA / ADD
#define HFMA2(d, a, b) \
    asm("fma.rn.f16x2 %0, %1, %2, %0;" : "+r"(d) : "r"(a), "r"(b))
#define HADD2(d, a, b) \
    asm("add.rn.f16x2 %0, %1, %2;" : "=r"(d) : "r"(a), "r"(b))

__device__ __forceinline__ uint32_t h2_bits(__half2 h) {
    uint32_t u; memcpy(&u, &h, 4); return u;
}
__device__ __forceinline__ __half2 bits_h2(uint32_t u) {
    __half2 h; memcpy(&h, &u, 4); return h;
}

// Scratch (allocation-free rule: __device__ globals)
__device__ int     g_cnt[N_NODES];                       // in-degree counters
__device__ float2  g_csr[(size_t)N_NODES * BUCKET];      // buckets (src_bits, ex)
__device__ __half2 g_gh[(size_t)N_NODES * 32];           // feat @ W_neigh^T (fp16)

// ---------------------------------------------------------------------------
// K1: single-pass bucket build (R12-proven).
// ---------------------------------------------------------------------------
__global__ void place_kernel(const float* __restrict__ rel,
                             const float* __restrict__ attn,
                             const int*   __restrict__ src,
                             const int*   __restrict__ dst) {
    int i = (blockIdx.x * blockDim.x + threadIdx.x) * 2;
    if (i >= N_EDGES) return;
    float a0 = __ldg(&attn[0]);
    float a1 = __ldg(&attn[1]);
    float4 r = *reinterpret_cast<const float4*>(rel + i * 2);  // edges i, i+1
    int2 s2 = *reinterpret_cast<const int2*>(src + i);
    int2 d2 = *reinterpret_cast<const int2*>(dst + i);

    float e0 = r.x * a0 + r.y * a1;
    float e1 = r.z * a0 + r.w * a1;
    e0 = (e0 > 0.0f) ? e0 : NEG_SLOPE * e0;
    e1 = (e1 > 0.0f) ? e1 : NEG_SLOPE * e1;
    float ex0 = __expf(e0);
    float ex1 = __expf(e1);

    int p0 = atomicAdd(&g_cnt[d2.x], 1);
    int p1 = atomicAdd(&g_cnt[d2.y], 1);
    if (p0 < BUCKET)
        g_csr[(size_t)d2.x * BUCKET + p0] = make_float2(__int_as_float(s2.x), ex0);
    if (p1 < BUCKET)
        g_csr[(size_t)d2.y * BUCKET + p1] = make_float2(__int_as_float(s2.y), ex1);
}

// ---------------------------------------------------------------------------
// K2: fused dual GEMM via mma.sync (m16n8k16 fp16 -> fp32).
//   Tile: 64 nodes x 128 outputs (cols 0-63 self, 64-127 neigh), K = 64.
//   A = feat (fp16, smem [64][72] pitch kills conflicts)
//   B = [Ws ; Wn] (fp16, smem [128][72], [n][k] = col-major for row.col)
//   Warp w handles nodes w*16 .. w*16+15 (16 N-tiles of 8, 4 K-steps).
//   Epilogue: self + bias -> out (direct store), neigh -> fp16 g_gh.
// ---------------------------------------------------------------------------
#define APITCH 72
__global__ __launch_bounds__(128) void hmma_gemm_kernel(
    const float* __restrict__ feat,
    const float* __restrict__ Ws, const float* __restrict__ bs,
    const float* __restrict__ Wn, const float* __restrict__ bn,
    float* __restrict__ out) {
    __shared__ __half sA[64][APITCH];
    __shared__ __half sB[128][APITCH];
    __shared__ float  sBias[64];

    const int t = threadIdx.x;
    const int w = t >> 5, lane = t & 31;
    const int g = lane >> 2, tq = lane & 3;
    const int nodeBase = blockIdx.x * 64;

    if (t < 64) sBias[t] = __ldg(&bs[t]) + __ldg(&bn[t]);

    // A: feat tile, fp32 -> fp16
    for (int i = t; i < 1024; i += 128) {
        int row = i >> 4, q = i & 15;
        int node = nodeBase + row;
        float4 v = (node < N_NODES)
                       ? reinterpret_cast<const float4*>(feat)[(size_t)node * 16 + q]
                       : make_float4(0.f, 0.f, 0.f, 0.f);
        *reinterpret_cast<uint2*>(&sA[row][q * 4]) =
            make_uint2(h2_bits(__floats2half2_rn(v.x, v.y)),
                       h2_bits(__floats2half2_rn(v.z, v.w)));
    }
    // B: rows 0-63 = Ws, 64-127 = Wn  (row n holds W[n][k], k contiguous)
    for (int i = t; i < 2048; i += 128) {
        int row = i >> 4, q = i & 15;
        const float* W = (row < 64) ? Ws : Wn;
        float4 v = reinterpret_cast<const float4*>(W)[(row & 63) * 16 + q];
        *reinterpret_cast<uint2*>(&sB[row][q * 4]) =
            make_uint2(h2_bits(__floats2half2_rn(v.x, v.y)),
                       h2_bits(__floats2half2_rn(v.z, v.w)));
    }
    __syncthreads();

    float d[16][4];
    #pragma unroll
    for (int nt = 0; nt < 16; nt++)
        d[nt][0] = d[nt][1] = d[nt][2] = d[nt][3] = 0.f;

    #pragma unroll
    for (int ks = 0; ks < 4; ks++) {
        const __half* pa = &sA[w * 16 + g][ks * 16 + tq * 2];
        uint32_t a0 = *reinterpret_cast<const uint32_t*>(pa);
        uint32_t a1 = *reinterpret_cast<const uint32_t*>(pa + 8 * APITCH);
        uint32_t a2 = *reinterpret_cast<const uint32_t*>(pa + 8);
        uint32_t a3 = *reinterpret_cast<const uint32_t*>(pa + 8 * APITCH + 8);
        #pragma unroll
        for (int nt = 0; nt < 16; nt++) {
            const __half* pb = &sB[nt * 8 + g][ks * 16 + tq * 2];
            uint32_t b0 = *reinterpret_cast<const uint32_t*>(pb);
            uint32_t b1 = *reinterpret_cast<const uint32_t*>(pb + 8);
            asm volatile(
                "mma.sync.aligned.m16n8k16.row.col.f32.f16.f16.f32 "
                "{%0,%1,%2,%3}, {%4,%5,%6,%7}, {%8,%9}, {%0,%1,%2,%3};"
                : "+f"(d[nt][0]), "+f"(d[nt][1]), "+f"(d[nt][2]), "+f"(d[nt][3])
                : "r"(a0), "r"(a1), "r"(a2), "r"(a3), "r"(b0), "r"(b1));
        }
    }

    const int node0 = nodeBase + w * 16 + g;
    const int node1 = node0 + 8;
    const bool v0 = node0 < N_NODES, v1 = node1 < N_NODES;

    // self half: cols 0-63, + bias -> out
    #pragma unroll
    for (int nt = 0; nt < 8; nt++) {
        int col = nt * 8 + tq * 2;
        float b0f = sBias[col], b1f = sBias[col + 1];
        if (v0)
            *reinterpret_cast<float2*>(out + (size_t)node0 * D + col) =
                make_float2(d[nt][0] + b0f, d[nt][1] + b1f);
        if (v1)
            *reinterpret_cast<float2*>(out + (size_t)node1 * D + col) =
                make_float2(d[nt][2] + b0f, d[nt][3] + b1f);
    }
    // neigh half: cols 64-127 -> fp16 g_gh
    #pragma unroll
    for (int nt = 8; nt < 16; nt++) {
        int ci = (nt - 8) * 4 + tq;       // half2 index within row
        if (v0)
            *reinterpret_cast<uint32_t*>(&g_gh[(size_t)node0 * 32 + ci]) =
                h2_bits(__floats2half2_rn(d[nt][0], d[nt][1]));
        if (v1)
            *reinterpret_cast<uint32_t*>(&g_gh[(size_t)node1 * 32 + ci]) =
                h2_bits(__floats2half2_rn(d[nt][2], d[nt][3]));
    }
}

// ---------------------------------------------------------------------------
// K3: gather-aggregate (R12-proven). Warp/node, fp16 HFMA2, in-register sum.
//   lane = h*8 + c : h = edge slot (4 edges/step), c = dim group (8 dims).
//   RED-adds onto out (already holding self+bias from hmma_gemm).
// ---------------------------------------------------------------------------
__global__ __launch_bounds__(256) void aggregate_kernel(float* __restrict__ out) {
    int node = (blockIdx.x * blockDim.x + threadIdx.x) >> 5;
    if (node >= N_NODES) return;
    const int lane = threadIdx.x & 31;
    const int h = lane >> 3;       // edge slot 0..3
    const int c = lane & 7;        // dim group (8 dims)

    int cnt = g_cnt[node];
    if (cnt == 0) return;
    if (cnt > BUCKET) cnt = BUCKET;
    const float2* bucket = &g_csr[(size_t)node * BUCKET];

    uint32_t acc0 = 0, acc1 = 0, acc2 = 0, acc3 = 0;   // half2 accumulators
    float sum = 0.f;

    #pragma unroll 2
    for (int j = 0; j < cnt; j += 4) {
        int idx = j + h;
        float2 p = (idx < cnt) ? __ldg(&bucket[idx])
                               : make_float2(__int_as_float(0), 0.f);
        uint4 hv = __ldg(reinterpret_cast<const uint4*>(
            &g_gh[(size_t)__float_as_int(p.x) * 32 + c * 4]));
        uint32_t wh = h2_bits(__float2half2_rn(p.y));
        HFMA2(acc0, hv.x, wh);
        HFMA2(acc1, hv.y, wh);
        HFMA2(acc2, hv.z, wh);
        HFMA2(acc3, hv.w, wh);
        sum += p.y;
    }

    uint32_t o0, o1, o2, o3;
    o0 = __shfl_xor_sync(0xffffffffu, acc0, 8);  HADD2(acc0, acc0, o0);
    o1 = __shfl_xor_sync(0xffffffffu, acc1, 8);  HADD2(acc1, acc1, o1);
    o2 = __shfl_xor_sync(0xffffffffu, acc2, 8);  HADD2(acc2, acc2, o2);
    o3 = __shfl_xor_sync(0xffffffffu, acc3, 8);  HADD2(acc3, acc3, o3);
    o0 = __shfl_xor_sync(0xffffffffu, acc0, 16); HADD2(acc0, acc0, o0);
    o1 = __shfl_xor_sync(0xffffffffu, acc1, 16); HADD2(acc1, acc1, o1);
    o2 = __shfl_xor_sync(0xffffffffu, acc2, 16); HADD2(acc2, acc2, o2);
    o3 = __shfl_xor_sync(0xffffffffu, acc3, 16); HADD2(acc3, acc3, o3);
    sum += __shfl_xor_sync(0xffffffffu, sum, 8);
    sum += __shfl_xor_sync(0xffffffffu, sum, 16);

    if (h == 0) {
        const float inv = 1.0f / sum;
        float2 f0 = __half22float2(bits_h2(acc0));
        float2 f1 = __half22float2(bits_h2(acc1));
        float2 f2 = __half22float2(bits_h2(acc2));
        float2 f3 = __half22float2(bits_h2(acc3));
        float* p = out + (size_t)node * D + c * 8;
        asm volatile("red.global.add.v4.f32 [%0], {%1,%2,%3,%4};"
                     :: "l"(p), "f"(f0.x * inv), "f"(f0.y * inv),
                        "f"(f1.x * inv), "f"(f1.y * inv) : "memory");
        asm volatile("red.global.add.v4.f32 [%0], {%1,%2,%3,%4};"
                     :: "l"(p + 4), "f"(f2.x * inv), "f"(f2.y * inv),
                        "f"(f3.x * inv), "f"(f3.y * inv) : "memory");
    }
}

// ---------------------------------------------------------------------------
// Launch:  s2: hmma_gemm --evG-->           (writes out = self+bias, g_gh)
//          main: memset cnt; place; wait evG; aggregate (RED-adds onto out)
// ---------------------------------------------------------------------------
extern "C" void kernel_launch(void* const* d_in, const int* in_sizes, int n_in,
                              void* d_out, int out_size) {
    const float* feat = (const float*)d_in[0];
    const float* rel  = (const float*)d_in[1];
    const float* Ws   = (const float*)d_in[2];
    const float* bs   = (const float*)d_in[3];
    const float* Wn   = (const float*)d_in[4];
    const float* bn   = (const float*)d_in[5];
    const float* attn = (const float*)d_in[6];
    const int*   src  = (const int*)d_in[7];
    const int*   dst  = (const int*)d_in[8];
    float* out = (float*)d_out;

    static void*        cnt_addr = nullptr;
    static cudaStream_t s2;
    static cudaEvent_t  evFork, evG;
    if (!cnt_addr) {
        cudaGetSymbolAddress(&cnt_addr, g_cnt);
        cudaStreamCreateWithFlags(&s2, cudaStreamNonBlocking);
        cudaEventCreateWithFlags(&evFork, cudaEventDisableTiming);
        cudaEventCreateWithFlags(&evG,    cudaEventDisableTiming);
    }

    // Side stream: tensor-core fused GEMM (independent of edge path)
    cudaEventRecord(evFork, 0);
    cudaStreamWaitEvent(s2, evFork, 0);
    hmma_gemm_kernel<<<(N_NODES + 63) / 64, 128, 0, s2>>>(
        feat, Ws, bs, Wn, bn, out);
    cudaEventRecord(evG, s2);

    // Main: edge path
    cudaMemsetAsync(cnt_addr, 0, N_NODES * sizeof(int));
    place_kernel<<<(N_EDGES / 2 + 255) / 256, 256>>>(rel, attn, src, dst);

    // Aggregate needs hmma_gemm (out base + g_gh) and buckets
    cudaStreamWaitEvent(0, evG, 0);
    aggregate_kernel<<<(N_NODES * 32 + 255) / 256, 256>>>(out);
}